// round 6
// baseline (speedup 1.0000x reference)
#include <cuda_runtime.h>

#define KS 48
#define NT 256

typedef unsigned long long ull;

// strides (floats)
constexpr int SX_STRIDE  = 50;   // X[c][h] (even for ull loads)
constexpr int W_STRIDE   = 65;   // W-half [o][c]
constexpr int QKV_STRIDE = 49;   // QKV[o][h]
constexpr int REL_STRIDE = 95;   // rel[c][d] packed
constexpr int QK_STRIDE  = 50;   // QR/KR [48][50]
constexpr int SIM_STRIDE = 51;   // SIM   [48][51]
constexpr int OUT_STRIDE = 65;   // out[i][p]

constexpr int OFF_QKV = 0;                               // 6272
constexpr int OFF_REL = OFF_QKV + 128 * QKV_STRIDE;      // +1520
constexpr int OFF_OUT = OFF_REL + 16 * REL_STRIDE;       // +3120
constexpr int OFF_PAR = OFF_OUT + 48 * OUT_STRIDE;       // +288
constexpr int OFF_SCR = OFF_PAR + 6 * 48;                // 11200
// phase 1 scratch: X (3200) + W-half (4160) = 7360
constexpr int OFF_X   = OFF_SCR;
constexpr int OFF_WH  = OFF_X + 64 * SX_STRIDE;
// phase 2 scratch (single group): QR 2400 + KR 2400 + SIM 2448 = 7248
constexpr int OFF_QR  = OFF_SCR;
constexpr int OFF_KR  = OFF_QR + 48 * QK_STRIDE;
constexpr int OFF_SIM = OFF_KR + 48 * QK_STRIDE;
constexpr int SCR_FLOATS  = 64 * SX_STRIDE + 64 * W_STRIDE;   // 7360 (>7248)
constexpr int SMEM_FLOATS = OFF_SCR + SCR_FLOATS;        // 18560
constexpr int SMEM_BYTES  = SMEM_FLOATS * 4;             // 74240 B -> 3 CTAs/SM

__device__ __forceinline__ ull dupf(float v) {
    ull r; unsigned u = __float_as_uint(v);
    asm("mov.b64 %0, {%1, %1};" : "=l"(r) : "r"(u));
    return r;
}
__device__ __forceinline__ void ffma2(ull& d, ull a, ull b) {
    asm("fma.rn.f32x2 %0, %1, %2, %0;" : "+l"(d) : "l"(a), "l"(b));
}
__device__ __forceinline__ float f2lo(ull v) { return __uint_as_float((unsigned)(v & 0xffffffffull)); }
__device__ __forceinline__ float f2hi(ull v) { return __uint_as_float((unsigned)(v >> 32)); }

__global__ void __launch_bounds__(NT, 3) axial_kernel(
    const float* __restrict__ x,      const float* __restrict__ w_qkv,
    const float* __restrict__ relv,
    const float* __restrict__ g_qkv,  const float* __restrict__ b_qkv,
    const float* __restrict__ g_sim,  const float* __restrict__ b_sim,
    const float* __restrict__ g_out,  const float* __restrict__ b_out,
    float* __restrict__ out)
{
    extern __shared__ float sm[];
    float* sX   = sm + OFF_X;
    float* sWh  = sm + OFF_WH;
    float* sQKV = sm + OFF_QKV;
    float* sRel = sm + OFF_REL;
    float* sOut = sm + OFF_OUT;
    float* sQR  = sm + OFF_QR;
    float* sKR  = sm + OFF_KR;
    float* sSim = sm + OFF_SIM;
    float* sGQ  = sm + OFF_PAR;
    float* sBQ  = sGQ + 48; float* sGS = sBQ + 48; float* sBS = sGS + 48;
    float* sGO  = sBS + 48; float* sBO = sGO + 48;

    const int tid = threadIdx.x;
    const int blk = blockIdx.x;
    const int wi = blk / KS, li = blk % KS;

    // ---- load X (as [c][h]), relative, BN params ----
    for (int idx = tid; idx < KS * 64; idx += NT) {
        const int h = idx >> 6, c = idx & 63;
        sX[c * SX_STRIDE + h] = x[((h * KS + wi) * KS + li) * 64 + c];
    }
    for (int idx = tid; idx < 16 * REL_STRIDE; idx += NT)
        sRel[idx] = relv[idx];
    if (tid < KS) {
        const float inv = rsqrtf(1.001f);
        sGQ[tid] = g_qkv[tid] * inv; sBQ[tid] = b_qkv[tid];
        sGS[tid] = g_sim[tid] * inv; sBS[tid] = 3.0f * b_sim[tid];
        sGO[tid] = g_out[tid] * inv; sBO[tid] = 2.0f * b_out[tid];
    }

    // ---- QKV = BN(W @ X) in two 64-row halves (W staged in scratch) ----
    for (int half = 0; half < 2; ++half) {
        __syncthreads();   // X/params ready (half 0); prior compute done (half 1)
        for (int idx = tid; idx < 64 * 64; idx += NT)
            sWh[(idx >> 6) * W_STRIDE + (idx & 63)] = w_qkv[half * 64 * 64 + idx];
        __syncthreads();

        const int o0 = (tid >> 3) * 2;           // 0..62 within half
        const int h0 = (tid & 7) * 6;
        ull a[2][3];
        #pragma unroll
        for (int q = 0; q < 2; ++q)
            #pragma unroll
            for (int p = 0; p < 3; ++p) a[q][p] = 0ull;
        const float* xrow = sX + h0;
        #pragma unroll 4
        for (int c = 0; c < 64; ++c) {
            const ull* xp = reinterpret_cast<const ull*>(xrow + c * SX_STRIDE);
            const ull x01 = xp[0], x23 = xp[1], x45 = xp[2];
            #pragma unroll
            for (int q = 0; q < 2; ++q) {
                const ull wd = dupf(sWh[(o0 + q) * W_STRIDE + c]);
                ffma2(a[q][0], wd, x01);
                ffma2(a[q][1], wd, x23);
                ffma2(a[q][2], wd, x45);
            }
        }
        float gg[6], bb[6];
        #pragma unroll
        for (int p = 0; p < 6; ++p) { gg[p] = sGQ[h0 + p]; bb[p] = sBQ[h0 + p]; }
        #pragma unroll
        for (int q = 0; q < 2; ++q) {
            float* dst = sQKV + (half * 64 + o0 + q) * QKV_STRIDE + h0;
            #pragma unroll
            for (int p = 0; p < 3; ++p) {
                dst[2 * p]     = f2lo(a[q][p]) * gg[2 * p]     + bb[2 * p];
                dst[2 * p + 1] = f2hi(a[q][p]) * gg[2 * p + 1] + bb[2 * p + 1];
            }
        }
    }
    __syncthreads();

    // ---- 8 single-group passes ----
    for (int g = 0; g < 8; ++g) {
        const float* Qb = sQKV + (16 * g) * QKV_STRIDE;
        const float* Kb = Qb + 4 * QKV_STRIDE;
        const float* Vb = Qb + 8 * QKV_STRIDE;

        // == qr/kr: 768 sextet tasks, exactly 3 per thread ==
        #pragma unroll
        for (int k3 = 0; k3 < 3; ++k3) {
            const int task = tid + k3 * NT;
            if (task < 384) {
                const int m = task >> 3, i0 = (task & 7) * 6;
                float a0 = 0.f, a1 = 0.f, a2 = 0.f, a3 = 0.f, a4 = 0.f, a5 = 0.f;
                #pragma unroll
                for (int c = 0; c < 4; ++c) {
                    const float qc = Qb[c * QKV_STRIDE + m];
                    const float* rl = sRel + c * REL_STRIDE + (m - i0 + 47);
                    a0 += qc * rl[0];  a1 += qc * rl[-1]; a2 += qc * rl[-2];
                    a3 += qc * rl[-3]; a4 += qc * rl[-4]; a5 += qc * rl[-5];
                }
                float* d = sQR + m * QK_STRIDE + i0;
                d[0] = a0; d[1] = a1; d[2] = a2; d[3] = a3; d[4] = a4; d[5] = a5;
            } else {
                const int tk = task - 384;
                const int j = tk >> 3, m0 = (tk & 7) * 6;
                float a0 = 0.f, a1 = 0.f, a2 = 0.f, a3 = 0.f, a4 = 0.f, a5 = 0.f;
                #pragma unroll
                for (int c = 0; c < 4; ++c) {
                    const float kc = Kb[c * QKV_STRIDE + j];
                    const float* rl = sRel + (4 + c) * REL_STRIDE + (j - m0 + 47);
                    a0 += kc * rl[0];  a1 += kc * rl[-1]; a2 += kc * rl[-2];
                    a3 += kc * rl[-3]; a4 += kc * rl[-4]; a5 += kc * rl[-5];
                }
                float* d = sKR + m0 * QK_STRIDE + j;
                d[0] = a0;                  d[QK_STRIDE] = a1;
                d[2 * QK_STRIDE] = a2;      d[3 * QK_STRIDE] = a3;
                d[4 * QK_STRIDE] = a4;      d[5 * QK_STRIDE] = a5;
            }
        }
        __syncthreads();

        // == qk: 64 6x6 tiles x 4 m-quarters; butterfly reduce; BN epilogue ==
        {
            const int mq   = tid & 3;
            const int tile = tid >> 2;                       // 0..63
            const int i0   = (tile & 3) * 6 + (tile >> 5) * 24;
            const int j0   = ((tile >> 2) & 7) * 6;

            ull acc[3][6];
            #pragma unroll
            for (int p = 0; p < 3; ++p)
                #pragma unroll
                for (int jj = 0; jj < 6; ++jj) acc[p][jj] = 0ull;

            const int mb = mq * 12;
            #pragma unroll 4
            for (int mm = 0; mm < 12; ++mm) {
                const float* qp = sQR + (mb + mm) * QK_STRIDE + i0;
                const ull q01 = reinterpret_cast<const ull*>(qp)[0];
                const ull q23 = reinterpret_cast<const ull*>(qp)[1];
                const ull q45 = reinterpret_cast<const ull*>(qp)[2];
                const float* kp = sKR + (mb + mm) * QK_STRIDE + j0;
                #pragma unroll
                for (int jj = 0; jj < 6; ++jj) {
                    const ull kd = dupf(kp[jj]);
                    ffma2(acc[0][jj], q01, kd);
                    ffma2(acc[1][jj], q23, kd);
                    ffma2(acc[2][jj], q45, kd);
                }
            }
            #pragma unroll
            for (int p = 0; p < 3; ++p) {
                float f0[6], f1[6];
                #pragma unroll
                for (int jj = 0; jj < 6; ++jj) {
                    const ull o = __shfl_xor_sync(0xffffffffu, acc[p][jj], 1);
                    f0[jj] = f2lo(acc[p][jj]) + f2lo(o);
                    f1[jj] = f2hi(acc[p][jj]) + f2hi(o);
                }
                #pragma unroll
                for (int jj = 0; jj < 6; ++jj) {
                    f0[jj] += __shfl_xor_sync(0xffffffffu, f0[jj], 2);
                    f1[jj] += __shfl_xor_sync(0xffffffffu, f1[jj], 2);
                }
                const int r0 = 2 * p, r1 = 2 * p + 1;
                if (mq == (r0 & 3)) {
                    const int i = i0 + r0;
                    const float* qrow = sQR + i * QK_STRIDE + j0;
                    const float* krow = sKR + i * QK_STRIDE + j0;
                    float* srow = sSim + i * SIM_STRIDE + j0;
                    #pragma unroll
                    for (int jj = 0; jj < 6; ++jj) {
                        const int j = j0 + jj;
                        srow[jj] = (f0[jj] + qrow[jj] + krow[jj]) * sGS[j] + sBS[j];
                    }
                }
                if (mq == (r1 & 3)) {
                    const int i = i0 + r1;
                    const float* qrow = sQR + i * QK_STRIDE + j0;
                    const float* krow = sKR + i * QK_STRIDE + j0;
                    float* srow = sSim + i * SIM_STRIDE + j0;
                    #pragma unroll
                    for (int jj = 0; jj < 6; ++jj) {
                        const int j = j0 + jj;
                        srow[jj] = (f1[jj] + qrow[jj] + krow[jj]) * sGS[j] + sBS[j];
                    }
                }
            }
        }
        __syncthreads();

        // == softmax over j; 48 rows over 8 warps ==
        {
            const int lane = tid & 31, wp = tid >> 5;
            for (int r = wp; r < KS; r += 8) {
                float* row = sSim + r * SIM_STRIDE;
                const float v0 = row[lane];
                const float v1 = (lane < 16) ? row[32 + lane] : -3.0e38f;
                float mx = fmaxf(v0, v1);
                #pragma unroll
                for (int off = 16; off > 0; off >>= 1)
                    mx = fmaxf(mx, __shfl_xor_sync(0xffffffffu, mx, off));
                const float e0 = __expf(v0 - mx);
                const float e1 = (lane < 16) ? __expf(v1 - mx) : 0.f;
                float sumv = e0 + e1;
                #pragma unroll
                for (int off = 16; off > 0; off >>= 1)
                    sumv += __shfl_xor_sync(0xffffffffu, sumv, off);
                const float rinv = __fdividef(1.0f, sumv);
                row[lane] = e0 * rinv;
                if (lane < 16) row[32 + lane] = e1 * rinv;
            }
        }
        __syncthreads();

        // == sv: 32 tiles (4c x 3i) x 8 j-splits; butterfly reduce ==
        {
            const int jq   = tid & 7;
            const int tile = tid >> 3;                 // 0..31
            const int c0   = (tile & 1) * 4;
            const int i0   = (tile >> 1) * 3;          // 0..45
            const int jb   = jq * 6;

            float w[4][8];
            #pragma unroll
            for (int cc = 0; cc < 4; ++cc) {
                const float* base = sRel + (8 + c0 + cc) * REL_STRIDE + (i0 - jb + 42);
                #pragma unroll
                for (int t = 0; t < 8; ++t) w[cc][t] = base[t];
            }

            float acc[4][3];
            #pragma unroll
            for (int cc = 0; cc < 4; ++cc)
                #pragma unroll
                for (int ii = 0; ii < 3; ++ii) acc[cc][ii] = 0.f;

            #pragma unroll
            for (int jj = 0; jj < 6; ++jj) {
                const int j = jb + jj;
                const float s0 = sSim[i0 * SIM_STRIDE + j];
                const float s1 = sSim[(i0 + 1) * SIM_STRIDE + j];
                const float s2 = sSim[(i0 + 2) * SIM_STRIDE + j];
                #pragma unroll
                for (int cc = 0; cc < 4; ++cc) {
                    const float vv = Vb[(c0 + cc) * QKV_STRIDE + j];
                    acc[cc][0] += s0 * (vv + w[cc][5 - jj]);
                    acc[cc][1] += s1 * (vv + w[cc][6 - jj]);
                    acc[cc][2] += s2 * (vv + w[cc][7 - jj]);
                }
            }
            #pragma unroll
            for (int cc = 0; cc < 4; ++cc)
                #pragma unroll
                for (int ii = 0; ii < 3; ++ii) {
                    acc[cc][ii] += __shfl_xor_sync(0xffffffffu, acc[cc][ii], 1);
                    acc[cc][ii] += __shfl_xor_sync(0xffffffffu, acc[cc][ii], 2);
                    acc[cc][ii] += __shfl_xor_sync(0xffffffffu, acc[cc][ii], 4);
                }
            // writes: lane jq -> (cc = jq&3, ii = jq>>2); lanes 0..3 also ii=2
            {
                const int ccw = jq & 3;
                const int iiw = jq >> 2;
                const float av =
                    (jq == 0) ? acc[0][0] : (jq == 1) ? acc[1][0] :
                    (jq == 2) ? acc[2][0] : (jq == 3) ? acc[3][0] :
                    (jq == 4) ? acc[0][1] : (jq == 5) ? acc[1][1] :
                    (jq == 6) ? acc[2][1] :             acc[3][1];
                const int i = i0 + iiw;
                sOut[i * OUT_STRIDE + 8 * g + c0 + ccw] = av * sGO[i] + sBO[i];
                if (jq < 4) {
                    const float av2 =
                        (jq == 0) ? acc[0][2] : (jq == 1) ? acc[1][2] :
                        (jq == 2) ? acc[2][2] :             acc[3][2];
                    const int i2 = i0 + 2;
                    sOut[i2 * OUT_STRIDE + 8 * g + c0 + ccw] = av2 * sGO[i2] + sBO[i2];
                }
            }
        }
        __syncthreads();
    }

    // ---- write out: out[0, i, wi, li, p] (coalesced) ----
    for (int idx = tid; idx < KS * 64; idx += NT) {
        const int i = idx >> 6, p = idx & 63;
        out[((i * KS + wi) * KS + li) * 64 + p] = sOut[i * OUT_STRIDE + p];
    }
}

extern "C" void kernel_launch(void* const* d_in, const int* in_sizes, int n_in,
                              void* d_out, int out_size) {
    (void)in_sizes; (void)n_in; (void)out_size;
    cudaFuncSetAttribute(axial_kernel, cudaFuncAttributeMaxDynamicSharedMemorySize, SMEM_BYTES);
    axial_kernel<<<KS * KS, NT, SMEM_BYTES>>>(
        (const float*)d_in[0], (const float*)d_in[1], (const float*)d_in[2],
        (const float*)d_in[3], (const float*)d_in[4], (const float*)d_in[5],
        (const float*)d_in[6], (const float*)d_in[7], (const float*)d_in[8],
        (float*)d_out);
}

// round 7
// speedup vs baseline: 1.1408x; 1.1408x over previous
#include <cuda_runtime.h>

#define KS 48
#define NT 256

typedef unsigned long long ull;

// strides (floats)
constexpr int SX_STRIDE  = 50;   // X[c][h]
constexpr int W_STRIDE   = 65;   // W[o][c]
constexpr int QKV_STRIDE = 49;   // QKV[o][h]
constexpr int REL_STRIDE = 97;   // rel[c][d]
constexpr int QK_STRIDE  = 52;   // QR/KR [48][52]  (mult-4: LDS.128 in qk)
constexpr int SIM_STRIDE = 51;   // SIM   [48][51]
constexpr int OUT_STRIDE = 65;   // out[i][p]

constexpr int QK_G  = 48 * QK_STRIDE + 16;  // 2512 ≡16 mod 32: group-1 banks shifted
constexpr int SIM_G = 48 * SIM_STRIDE;      // 2448

constexpr int OFF_QKV = 0;                              // 6272
constexpr int OFF_REL = OFF_QKV + 128 * QKV_STRIDE;     // +1552
constexpr int OFF_OUT = OFF_REL + 16 * REL_STRIDE;      // +3120
constexpr int OFF_PAR = OFF_OUT + 48 * OUT_STRIDE;      // +288
constexpr int OFF_SCR = OFF_PAR + 6 * 48;               // 11232 (16B-aligned)
// phase 1 scratch: X (3200) + W (8320) = 11520
constexpr int OFF_X   = OFF_SCR;
constexpr int OFF_W   = OFF_X + 64 * SX_STRIDE;
// phase 2 scratch: QR/KR (2 groups, padded) + SIM (2 groups) = 14944
constexpr int OFF_QR  = OFF_SCR;
constexpr int OFF_KR  = OFF_QR + 2 * QK_G;
constexpr int OFF_SIM = OFF_KR + 2 * QK_G;
constexpr int SCR_FLOATS  = 4 * QK_G + 2 * SIM_G;        // 14944 > 11520
constexpr int SMEM_FLOATS = OFF_SCR + SCR_FLOATS;        // 26176
constexpr int SMEM_BYTES  = SMEM_FLOATS * 4;             // 104704 B -> 2 CTAs/SM

__device__ __forceinline__ ull dupf(float v) {
    ull r; unsigned u = __float_as_uint(v);
    asm("mov.b64 %0, {%1, %1};" : "=l"(r) : "r"(u));
    return r;
}
__device__ __forceinline__ void ffma2(ull& d, ull a, ull b) {
    asm("fma.rn.f32x2 %0, %1, %2, %0;" : "+l"(d) : "l"(a), "l"(b));
}
__device__ __forceinline__ float f2lo(ull v) { return __uint_as_float((unsigned)(v & 0xffffffffull)); }
__device__ __forceinline__ float f2hi(ull v) { return __uint_as_float((unsigned)(v >> 32)); }

__global__ void __launch_bounds__(NT, 2) axial_kernel(
    const float* __restrict__ x,      const float* __restrict__ w_qkv,
    const float* __restrict__ relv,
    const float* __restrict__ g_qkv,  const float* __restrict__ b_qkv,
    const float* __restrict__ g_sim,  const float* __restrict__ b_sim,
    const float* __restrict__ g_out,  const float* __restrict__ b_out,
    float* __restrict__ out)
{
    extern __shared__ float sm[];
    float* sX   = sm + OFF_X;
    float* sW   = sm + OFF_W;
    float* sQKV = sm + OFF_QKV;
    float* sRel = sm + OFF_REL;
    float* sOut = sm + OFF_OUT;
    float* sGQ  = sm + OFF_PAR;
    float* sBQ  = sGQ + 48; float* sGS = sBQ + 48; float* sBS = sGS + 48;
    float* sGO  = sBS + 48; float* sBO = sGO + 48;

    const int tid = threadIdx.x;
    const int blk = blockIdx.x;
    const int wi = blk / KS, li = blk % KS;

    // ---- load X (as [c][h]), W, relative, BN params ----
    for (int idx = tid; idx < KS * 64; idx += NT) {
        const int h = idx >> 6, c = idx & 63;
        sX[c * SX_STRIDE + h] = x[((h * KS + wi) * KS + li) * 64 + c];
    }
    for (int idx = tid; idx < 128 * 64; idx += NT)
        sW[(idx >> 6) * W_STRIDE + (idx & 63)] = w_qkv[idx];
    for (int idx = tid; idx < 16 * 95; idx += NT)
        sRel[(idx / 95) * REL_STRIDE + (idx % 95)] = relv[idx];
    if (tid < KS) {
        const float inv = rsqrtf(1.001f);
        sGQ[tid] = g_qkv[tid] * inv; sBQ[tid] = b_qkv[tid];
        sGS[tid] = g_sim[tid] * inv; sBS[tid] = 3.0f * b_sim[tid];
        sGO[tid] = g_out[tid] * inv; sBO[tid] = 2.0f * b_out[tid];
    }
    __syncthreads();

    // ---- QKV = BN(W @ X): 128x48, exact 4o x 6h tiles (256 tiles) ----
    {
        const int o0 = (tid >> 3) * 4;
        const int h0 = (tid & 7) * 6;
        ull a[4][3];
        #pragma unroll
        for (int q = 0; q < 4; ++q)
            #pragma unroll
            for (int p = 0; p < 3; ++p) a[q][p] = 0ull;
        const float* xrow = sX + h0;
        #pragma unroll 4
        for (int c = 0; c < 64; ++c) {
            const ull* xp = reinterpret_cast<const ull*>(xrow + c * SX_STRIDE);
            const ull x01 = xp[0], x23 = xp[1], x45 = xp[2];
            #pragma unroll
            for (int q = 0; q < 4; ++q) {
                const ull wd = dupf(sW[(o0 + q) * W_STRIDE + c]);
                ffma2(a[q][0], wd, x01);
                ffma2(a[q][1], wd, x23);
                ffma2(a[q][2], wd, x45);
            }
        }
        float gg[6], bb[6];
        #pragma unroll
        for (int p = 0; p < 6; ++p) { gg[p] = sGQ[h0 + p]; bb[p] = sBQ[h0 + p]; }
        #pragma unroll
        for (int q = 0; q < 4; ++q) {
            float* dst = sQKV + (o0 + q) * QKV_STRIDE + h0;
            #pragma unroll
            for (int p = 0; p < 3; ++p) {
                dst[2 * p]     = f2lo(a[q][p]) * gg[2 * p]     + bb[2 * p];
                dst[2 * p + 1] = f2hi(a[q][p]) * gg[2 * p + 1] + bb[2 * p + 1];
            }
        }
    }
    __syncthreads();

    // ---- 4 passes, 2 groups each ----
    for (int gp = 0; gp < 8; gp += 2) {

        // == qr/kr: 2304 quad-tasks, scattered-i (conflict-free rel windows) ==
        for (int q = tid; q < 2304; q += NT) {
            if (q < 1152) {
                const int grp = q / 576; const int r = q - grp * 576;
                const int m = r / 12, il = r % 12;
                const float* Q = sQKV + (16 * (gp + grp)) * QKV_STRIDE;
                float* QRg = sm + OFF_QR + grp * QK_G;
                float a0 = 0.f, a1 = 0.f, a2 = 0.f, a3 = 0.f;
                #pragma unroll
                for (int c = 0; c < 4; ++c) {
                    const float qc = Q[c * QKV_STRIDE + m];
                    const float* rl = sRel + c * REL_STRIDE + (m - il + 47);
                    a0 += qc * rl[0];   a1 += qc * rl[-12];
                    a2 += qc * rl[-24]; a3 += qc * rl[-36];
                }
                float* d = QRg + m * QK_STRIDE + il;
                d[0] = a0; d[12] = a1; d[24] = a2; d[36] = a3;
            } else {
                int r = q - 1152; const int grp = r / 576; r -= grp * 576;
                const int j = r / 12, ml = r % 12;
                const float* Kp = sQKV + (16 * (gp + grp) + 4) * QKV_STRIDE;
                float* KRg = sm + OFF_KR + grp * QK_G;
                float a0 = 0.f, a1 = 0.f, a2 = 0.f, a3 = 0.f;
                #pragma unroll
                for (int c = 0; c < 4; ++c) {
                    const float kc = Kp[c * QKV_STRIDE + j];
                    const float* rl = sRel + (4 + c) * REL_STRIDE + (j - ml + 47);
                    a0 += kc * rl[0];   a1 += kc * rl[-12];
                    a2 += kc * rl[-24]; a3 += kc * rl[-36];
                }
                KRg[ml * QK_STRIDE + j]        = a0;
                KRg[(ml + 12) * QK_STRIDE + j] = a1;
                KRg[(ml + 24) * QK_STRIDE + j] = a2;
                KRg[(ml + 36) * QK_STRIDE + j] = a3;
            }
        }
        __syncthreads();

        // == qk: 12i x 4j tiles via LDS.128, m-split 2, minimal pair exchange ==
        if (tid < 192) {
            const int mhalf = tid & 1;
            const int tile  = tid >> 1;          // 0..95
            const int grp   = tile / 48;
            const int u     = tile - grp * 48;
            const int i0    = (u & 3) * 12;
            const int j0    = (u >> 2) * 4;
            const float* QRg = sm + OFF_QR + grp * QK_G;
            const float* KRg = sm + OFF_KR + grp * QK_G;
            float* SIMg = sm + OFF_SIM + grp * SIM_G;

            ull acc[6][4];                       // [i-pair p][j]
            #pragma unroll
            for (int p = 0; p < 6; ++p)
                #pragma unroll
                for (int jj = 0; jj < 4; ++jj) acc[p][jj] = 0ull;

            const int mbase = mhalf * 24;
            #pragma unroll 4
            for (int mm = 0; mm < 24; ++mm) {
                const float* qp = QRg + (mbase + mm) * QK_STRIDE + i0;
                const ulonglong2 qa = *reinterpret_cast<const ulonglong2*>(qp);
                const ulonglong2 qb = *reinterpret_cast<const ulonglong2*>(qp + 4);
                const ulonglong2 qc = *reinterpret_cast<const ulonglong2*>(qp + 8);
                const float4 kv = *reinterpret_cast<const float4*>(
                    KRg + (mbase + mm) * QK_STRIDE + j0);
                const ull kd[4] = {dupf(kv.x), dupf(kv.y), dupf(kv.z), dupf(kv.w)};
                #pragma unroll
                for (int jj = 0; jj < 4; ++jj) {
                    ffma2(acc[0][jj], qa.x, kd[jj]);
                    ffma2(acc[1][jj], qa.y, kd[jj]);
                    ffma2(acc[2][jj], qb.x, kd[jj]);
                    ffma2(acc[3][jj], qb.y, kd[jj]);
                    ffma2(acc[4][jj], qc.x, kd[jj]);
                    ffma2(acc[5][jj], qc.y, kd[jj]);
                }
            }

            // exchange only the 12 ull each lane needs; lane owns p-range by mhalf
            const int pown = mhalf * 3;          // owned p: pown..pown+2
            #pragma unroll
            for (int t = 0; t < 3; ++t) {
                #pragma unroll
                for (int jj = 0; jj < 4; ++jj) {
                    const ull send = mhalf ? acc[t][jj] : acc[t + 3][jj];
                    const ull got  = __shfl_xor_sync(0xffffffffu, send, 1);
                    const int p = pown + t;
                    const float lo = f2lo(acc[p][jj]) + f2lo(got);
                    const float hi = f2hi(acc[p][jj]) + f2hi(got);
                    acc[p][jj] = ((ull)__float_as_uint(hi) << 32) | __float_as_uint(lo);
                }
            }

            // epilogue: owned rows i = i0+2p, i0+2p+1 for p in [pown, pown+3)
            const float4 gsv = *reinterpret_cast<const float4*>(sGS + j0);
            const float4 bsv = *reinterpret_cast<const float4*>(sBS + j0);
            const float gs4[4] = {gsv.x, gsv.y, gsv.z, gsv.w};
            const float bs4[4] = {bsv.x, bsv.y, bsv.z, bsv.w};
            #pragma unroll
            for (int t = 0; t < 3; ++t) {
                const int p = pown + t;
                const int ia = i0 + 2 * p, ib = ia + 1;
                const float4 qra = *reinterpret_cast<const float4*>(QRg + ia * QK_STRIDE + j0);
                const float4 qrb = *reinterpret_cast<const float4*>(QRg + ib * QK_STRIDE + j0);
                const float4 kra = *reinterpret_cast<const float4*>(KRg + ia * QK_STRIDE + j0);
                const float4 krb = *reinterpret_cast<const float4*>(KRg + ib * QK_STRIDE + j0);
                const float qa4[4] = {qra.x, qra.y, qra.z, qra.w};
                const float qb4[4] = {qrb.x, qrb.y, qrb.z, qrb.w};
                const float ka4[4] = {kra.x, kra.y, kra.z, kra.w};
                const float kb4[4] = {krb.x, krb.y, krb.z, krb.w};
                float* sa = SIMg + ia * SIM_STRIDE + j0;
                float* sb = SIMg + ib * SIM_STRIDE + j0;
                #pragma unroll
                for (int jj = 0; jj < 4; ++jj) {
                    sa[jj] = (f2lo(acc[p][jj]) + qa4[jj] + ka4[jj]) * gs4[jj] + bs4[jj];
                    sb[jj] = (f2hi(acc[p][jj]) + qb4[jj] + kb4[jj]) * gs4[jj] + bs4[jj];
                }
            }
        }
        __syncthreads();

        // == softmax: 96 rows as 48 pairs; 16 lanes/row, 3 j per lane ==
        {
            const int lane = tid & 31, wp = tid >> 5;
            const int half16 = lane >> 4;
            const int jb = (lane & 15) * 3;
            for (int rp = wp; rp < 48; rp += 8) {
                float* row = sm + OFF_SIM + (2 * rp + half16) * SIM_STRIDE;
                const float v0 = row[jb], v1 = row[jb + 1], v2 = row[jb + 2];
                float mx = fmaxf(v0, fmaxf(v1, v2));
                #pragma unroll
                for (int off = 1; off < 16; off <<= 1)
                    mx = fmaxf(mx, __shfl_xor_sync(0xffffffffu, mx, off));
                const float e0 = __expf(v0 - mx);
                const float e1 = __expf(v1 - mx);
                const float e2 = __expf(v2 - mx);
                float s = e0 + e1 + e2;
                #pragma unroll
                for (int off = 1; off < 16; off <<= 1)
                    s += __shfl_xor_sync(0xffffffffu, s, off);
                const float rinv = __fdividef(1.0f, s);
                row[jb] = e0 * rinv; row[jb + 1] = e1 * rinv; row[jb + 2] = e2 * rinv;
            }
        }
        __syncthreads();

        // == sv: 4c x 3i tiles x 4 j-splits; rel windows preloaded, shfl reduce ==
        {
            const int jq   = tid & 3;
            const int tile = tid >> 2;           // 0..63
            const int grp  = tile >> 5;
            const int tt   = tile & 31;
            const int c0   = (tt >> 4) * 4;
            const int i0   = (tt & 15) * 3;
            const float* SIMg = sm + OFF_SIM + grp * SIM_G;
            const float* V = sQKV + (16 * (gp + grp) + 8) * QKV_STRIDE;
            const int jb = jq * 12;

            float w[4][14];
            #pragma unroll
            for (int cc = 0; cc < 4; ++cc) {
                const float* base = sRel + (8 + c0 + cc) * REL_STRIDE + (i0 - jb + 36);
                #pragma unroll
                for (int t = 0; t < 14; ++t) w[cc][t] = base[t];
            }

            float acc[4][3];
            #pragma unroll
            for (int cc = 0; cc < 4; ++cc)
                #pragma unroll
                for (int ii = 0; ii < 3; ++ii) acc[cc][ii] = 0.f;

            #pragma unroll
            for (int jj = 0; jj < 12; ++jj) {
                const int j = jb + jj;
                const float s0 = SIMg[i0 * SIM_STRIDE + j];
                const float s1 = SIMg[(i0 + 1) * SIM_STRIDE + j];
                const float s2 = SIMg[(i0 + 2) * SIM_STRIDE + j];
                #pragma unroll
                for (int cc = 0; cc < 4; ++cc) {
                    const float vv = V[(c0 + cc) * QKV_STRIDE + j];
                    acc[cc][0] += s0 * (vv + w[cc][11 - jj]);
                    acc[cc][1] += s1 * (vv + w[cc][12 - jj]);
                    acc[cc][2] += s2 * (vv + w[cc][13 - jj]);
                }
            }
            #pragma unroll
            for (int cc = 0; cc < 4; ++cc)
                #pragma unroll
                for (int ii = 0; ii < 3; ++ii) {
                    acc[cc][ii] += __shfl_xor_sync(0xffffffffu, acc[cc][ii], 1);
                    acc[cc][ii] += __shfl_xor_sync(0xffffffffu, acc[cc][ii], 2);
                }
            const int c = c0 + jq;
            #pragma unroll
            for (int ii = 0; ii < 3; ++ii) {
                const float av = (jq == 0) ? acc[0][ii] :
                                 (jq == 1) ? acc[1][ii] :
                                 (jq == 2) ? acc[2][ii] : acc[3][ii];
                const int i = i0 + ii;
                sOut[i * OUT_STRIDE + 8 * (gp + grp) + c] = av * sGO[i] + sBO[i];
            }
        }
        __syncthreads();
    }

    // ---- write out: out[0, i, wi, li, p] ----
    for (int idx = tid; idx < KS * 64; idx += NT) {
        const int i = idx >> 6, p = idx & 63;
        out[((i * KS + wi) * KS + li) * 64 + p] = sOut[i * OUT_STRIDE + p];
    }
}

extern "C" void kernel_launch(void* const* d_in, const int* in_sizes, int n_in,
                              void* d_out, int out_size) {
    (void)in_sizes; (void)n_in; (void)out_size;
    cudaFuncSetAttribute(axial_kernel, cudaFuncAttributeMaxDynamicSharedMemorySize, SMEM_BYTES);
    axial_kernel<<<KS * KS, NT, SMEM_BYTES>>>(
        (const float*)d_in[0], (const float*)d_in[1], (const float*)d_in[2],
        (const float*)d_in[3], (const float*)d_in[4], (const float*)d_in[5],
        (const float*)d_in[6], (const float*)d_in[7], (const float*)d_in[8],
        (float*)d_out);
}

// round 8
// speedup vs baseline: 1.3433x; 1.1775x over previous
#include <cuda_runtime.h>

#define KS 48
#define NT 256

typedef unsigned long long ull;

// strides (floats)
constexpr int SX_STRIDE  = 50;   // X[c][h]
constexpr int W_STRIDE   = 65;   // W[o][c]
constexpr int QKV_STRIDE = 49;   // QKV[o][h]
constexpr int REL_STRIDE = 97;   // rel[c][d]
constexpr int QK_STRIDE  = 50;   // QR/KR [48][50]  (even: ull loads)
constexpr int SIM_STRIDE = 51;   // SIM   [48][51]
constexpr int OUT_STRIDE = 65;   // out[i][p]

constexpr int QK_G  = 48 * QK_STRIDE + 16;  // 2416: ≡16 mod 32 (kills qk 2-way conflicts)
constexpr int SIM_G = 48 * SIM_STRIDE;      // 2448 (contiguous groups for softmax)

constexpr int OFF_QKV = 0;                              // 6272
constexpr int OFF_REL = OFF_QKV + 128 * QKV_STRIDE;     // +1552
constexpr int OFF_OUT = OFF_REL + 16 * REL_STRIDE;      // +3120
constexpr int OFF_PAR = OFF_OUT + 48 * OUT_STRIDE;      // +288
constexpr int OFF_SCR = OFF_PAR + 6 * 48;               // 11232
// phase 1 scratch: X (3200) + W (8320) = 11520
constexpr int OFF_X   = OFF_SCR;
constexpr int OFF_W   = OFF_X + 64 * SX_STRIDE;
// phase 2 scratch: QR/KR (2 groups, padded) + SIM (2 groups) = 14560
constexpr int OFF_QR  = OFF_SCR;
constexpr int OFF_KR  = OFF_QR + 2 * QK_G;
constexpr int OFF_SIM = OFF_KR + 2 * QK_G;
constexpr int SCR_FLOATS  = 4 * QK_G + 2 * SIM_G;        // 14560 > 11520
constexpr int SMEM_FLOATS = OFF_SCR + SCR_FLOATS;        // 25792
constexpr int SMEM_BYTES  = SMEM_FLOATS * 4;             // 103168 B -> 2 CTAs/SM

__device__ __forceinline__ ull dupf(float v) {
    ull r; unsigned u = __float_as_uint(v);
    asm("mov.b64 %0, {%1, %1};" : "=l"(r) : "r"(u));
    return r;
}
__device__ __forceinline__ void ffma2(ull& d, ull a, ull b) {
    asm("fma.rn.f32x2 %0, %1, %2, %0;" : "+l"(d) : "l"(a), "l"(b));
}
__device__ __forceinline__ float f2lo(ull v) { return __uint_as_float((unsigned)(v & 0xffffffffull)); }
__device__ __forceinline__ float f2hi(ull v) { return __uint_as_float((unsigned)(v >> 32)); }

__global__ void __launch_bounds__(NT, 2) axial_kernel(
    const float* __restrict__ x,      const float* __restrict__ w_qkv,
    const float* __restrict__ relv,
    const float* __restrict__ g_qkv,  const float* __restrict__ b_qkv,
    const float* __restrict__ g_sim,  const float* __restrict__ b_sim,
    const float* __restrict__ g_out,  const float* __restrict__ b_out,
    float* __restrict__ out)
{
    extern __shared__ float sm[];
    float* sX   = sm + OFF_X;
    float* sW   = sm + OFF_W;
    float* sQKV = sm + OFF_QKV;
    float* sRel = sm + OFF_REL;
    float* sOut = sm + OFF_OUT;
    float* sGQ  = sm + OFF_PAR;
    float* sBQ  = sGQ + 48; float* sGS = sBQ + 48; float* sBS = sGS + 48;
    float* sGO  = sBS + 48; float* sBO = sGO + 48;

    const int tid = threadIdx.x;
    const int blk = blockIdx.x;
    const int wi = blk / KS, li = blk % KS;

    // ---- load X (as [c][h]), W, relative, BN params ----
    for (int idx = tid; idx < KS * 64; idx += NT) {
        const int h = idx >> 6, c = idx & 63;
        sX[c * SX_STRIDE + h] = x[((h * KS + wi) * KS + li) * 64 + c];
    }
    for (int idx = tid; idx < 128 * 64; idx += NT)
        sW[(idx >> 6) * W_STRIDE + (idx & 63)] = w_qkv[idx];
    for (int idx = tid; idx < 16 * 95; idx += NT)
        sRel[(idx / 95) * REL_STRIDE + (idx % 95)] = relv[idx];
    if (tid < KS) {
        const float inv = rsqrtf(1.001f);
        sGQ[tid] = g_qkv[tid] * inv; sBQ[tid] = b_qkv[tid];
        sGS[tid] = g_sim[tid] * inv; sBS[tid] = 3.0f * b_sim[tid];
        sGO[tid] = g_out[tid] * inv; sBO[tid] = 2.0f * b_out[tid];
    }
    __syncthreads();

    // ---- QKV = BN(W @ X): 128x48, exact 4o x 6h tiles (256 tiles) ----
    {
        const int o0 = (tid >> 3) * 4;
        const int h0 = (tid & 7) * 6;
        ull a[4][3];
        #pragma unroll
        for (int q = 0; q < 4; ++q)
            #pragma unroll
            for (int p = 0; p < 3; ++p) a[q][p] = 0ull;
        const float* xrow = sX + h0;
        #pragma unroll 4
        for (int c = 0; c < 64; ++c) {
            const ull* xp = reinterpret_cast<const ull*>(xrow + c * SX_STRIDE);
            const ull x01 = xp[0], x23 = xp[1], x45 = xp[2];
            #pragma unroll
            for (int q = 0; q < 4; ++q) {
                const ull wd = dupf(sW[(o0 + q) * W_STRIDE + c]);
                ffma2(a[q][0], wd, x01);
                ffma2(a[q][1], wd, x23);
                ffma2(a[q][2], wd, x45);
            }
        }
        float gg[6], bb[6];
        #pragma unroll
        for (int p = 0; p < 6; ++p) { gg[p] = sGQ[h0 + p]; bb[p] = sBQ[h0 + p]; }
        #pragma unroll
        for (int q = 0; q < 4; ++q) {
            float* dst = sQKV + (o0 + q) * QKV_STRIDE + h0;
            #pragma unroll
            for (int p = 0; p < 3; ++p) {
                dst[2 * p]     = f2lo(a[q][p]) * gg[2 * p]     + bb[2 * p];
                dst[2 * p + 1] = f2hi(a[q][p]) * gg[2 * p + 1] + bb[2 * p + 1];
            }
        }
    }
    __syncthreads();

    // ---- 4 passes, 2 groups each; all 256 threads cooperate on both ----
    for (int gp = 0; gp < 8; gp += 2) {

        // == qr/kr: 2304 quad-tasks, i (resp. m) strided by 12 -> rel loads
        //    are 14 consecutive warp addresses = conflict-free ==
        for (int q = tid; q < 2304; q += NT) {
            if (q < 1152) {
                const int grp = q / 576; const int r = q - grp * 576;
                const int m = r / 12, il = r % 12;
                const float* Q = sQKV + (16 * (gp + grp)) * QKV_STRIDE;
                float* QRg = sm + OFF_QR + grp * QK_G;
                float a0 = 0.f, a1 = 0.f, a2 = 0.f, a3 = 0.f;
                #pragma unroll
                for (int c = 0; c < 4; ++c) {
                    const float qc = Q[c * QKV_STRIDE + m];
                    const float* rl = sRel + c * REL_STRIDE + (m - il + 47);
                    a0 += qc * rl[0];   a1 += qc * rl[-12];
                    a2 += qc * rl[-24]; a3 += qc * rl[-36];
                }
                float* d = QRg + m * QK_STRIDE + il;
                d[0] = a0; d[12] = a1; d[24] = a2; d[36] = a3;
            } else {
                int r = q - 1152; const int grp = r / 576; r -= grp * 576;
                const int j = r / 12, ml = r % 12;
                const float* Kp = sQKV + (16 * (gp + grp) + 4) * QKV_STRIDE;
                float* KRg = sm + OFF_KR + grp * QK_G;
                float a0 = 0.f, a1 = 0.f, a2 = 0.f, a3 = 0.f;
                #pragma unroll
                for (int c = 0; c < 4; ++c) {
                    const float kc = Kp[c * QKV_STRIDE + j];
                    const float* rl = sRel + (4 + c) * REL_STRIDE + (j - ml + 47);
                    a0 += kc * rl[0];   a1 += kc * rl[-12];
                    a2 += kc * rl[-24]; a3 += kc * rl[-36];
                }
                KRg[ml * QK_STRIDE + j]        = a0;
                KRg[(ml + 12) * QK_STRIDE + j] = a1;
                KRg[(ml + 24) * QK_STRIDE + j] = a2;
                KRg[(ml + 36) * QK_STRIDE + j] = a3;
            }
        }
        __syncthreads();

        // == qk: 6x6 tiles, m-split over lane pairs, shfl reduce (float halves) ==
        {
            const int mhalf = tid & 1;
            const int tile  = tid >> 1;          // 0..127
            const int grp   = tile >> 6;
            const int tt    = tile & 63;
            const int i0    = (tt & 7) * 6;
            const int j0    = (tt >> 3) * 6;
            const float* QRg = sm + OFF_QR + grp * QK_G;
            const float* KRg = sm + OFF_KR + grp * QK_G;
            float* SIMg = sm + OFF_SIM + grp * SIM_G;

            ull acc[3][6];
            #pragma unroll
            for (int p = 0; p < 3; ++p)
                #pragma unroll
                for (int jj = 0; jj < 6; ++jj) acc[p][jj] = 0ull;

            const int mbase = mhalf * 24;
            #pragma unroll 4
            for (int mm = 0; mm < 24; ++mm) {
                const float* qp = QRg + (mbase + mm) * QK_STRIDE + i0;
                const ull q01 = reinterpret_cast<const ull*>(qp)[0];
                const ull q23 = reinterpret_cast<const ull*>(qp)[1];
                const ull q45 = reinterpret_cast<const ull*>(qp)[2];
                const float* kp = KRg + (mbase + mm) * QK_STRIDE + j0;
                #pragma unroll
                for (int jj = 0; jj < 6; ++jj) {
                    const ull kd = dupf(kp[jj]);
                    ffma2(acc[0][jj], q01, kd);
                    ffma2(acc[1][jj], q23, kd);
                    ffma2(acc[2][jj], q45, kd);
                }
            }
            // combine m-halves across the lane pair: shuffle packed, add as floats
            float full[6][6];   // [row within tile][j]
            #pragma unroll
            for (int p = 0; p < 3; ++p)
                #pragma unroll
                for (int jj = 0; jj < 6; ++jj) {
                    const ull other = __shfl_xor_sync(0xffffffffu, acc[p][jj], 1);
                    full[2 * p][jj]     = f2lo(acc[p][jj]) + f2lo(other);
                    full[2 * p + 1][jj] = f2hi(acc[p][jj]) + f2hi(other);
                }
            // each lane writes 3 rows: mhalf0 -> rows 0..2, mhalf1 -> rows 3..5
            const int rbase = mhalf * 3;
            #pragma unroll
            for (int rr = 0; rr < 3; ++rr) {
                const int i = i0 + rbase + rr;
                const float* qrow = QRg + i * QK_STRIDE + j0;
                const float* krow = KRg + i * QK_STRIDE + j0;
                float* srow = SIMg + i * SIM_STRIDE + j0;
                #pragma unroll
                for (int jj = 0; jj < 6; ++jj) {
                    const int j = j0 + jj;
                    const float v = full[rbase + rr][jj] + qrow[jj] + krow[jj];
                    srow[jj] = v * sGS[j] + sBS[j];
                }
            }
        }
        __syncthreads();

        // == softmax: 96 rows as 48 pairs; 16 lanes/row, 3 j per lane ==
        {
            const int lane = tid & 31, wp = tid >> 5;
            const int half16 = lane >> 4;
            const int jb = (lane & 15) * 3;
            for (int rp = wp; rp < 48; rp += 8) {
                float* row = sm + OFF_SIM + (2 * rp + half16) * SIM_STRIDE;
                const float v0 = row[jb], v1 = row[jb + 1], v2 = row[jb + 2];
                float mx = fmaxf(v0, fmaxf(v1, v2));
                #pragma unroll
                for (int off = 1; off < 16; off <<= 1)
                    mx = fmaxf(mx, __shfl_xor_sync(0xffffffffu, mx, off));
                const float e0 = __expf(v0 - mx);
                const float e1 = __expf(v1 - mx);
                const float e2 = __expf(v2 - mx);
                float s = e0 + e1 + e2;
                #pragma unroll
                for (int off = 1; off < 16; off <<= 1)
                    s += __shfl_xor_sync(0xffffffffu, s, off);
                const float rinv = __fdividef(1.0f, s);
                row[jb] = e0 * rinv; row[jb + 1] = e1 * rinv; row[jb + 2] = e2 * rinv;
            }
        }
        __syncthreads();

        // == sv: 4c x 3i tiles x 4 j-splits; rel windows preloaded, shfl reduce ==
        {
            const int jq   = tid & 3;
            const int tile = tid >> 2;           // 0..63
            const int grp  = tile >> 5;
            const int tt   = tile & 31;
            const int c0   = (tt >> 4) * 4;
            const int i0   = (tt & 15) * 3;
            const float* SIMg = sm + OFF_SIM + grp * SIM_G;
            const float* V = sQKV + (16 * (gp + grp) + 8) * QKV_STRIDE;
            const int jb = jq * 12;

            float w[4][14];
            #pragma unroll
            for (int cc = 0; cc < 4; ++cc) {
                const float* base = sRel + (8 + c0 + cc) * REL_STRIDE + (i0 - jb + 36);
                #pragma unroll
                for (int t = 0; t < 14; ++t) w[cc][t] = base[t];
            }

            float acc[4][3];
            #pragma unroll
            for (int cc = 0; cc < 4; ++cc)
                #pragma unroll
                for (int ii = 0; ii < 3; ++ii) acc[cc][ii] = 0.f;

            #pragma unroll
            for (int jj = 0; jj < 12; ++jj) {
                const int j = jb + jj;
                const float s0 = SIMg[i0 * SIM_STRIDE + j];
                const float s1 = SIMg[(i0 + 1) * SIM_STRIDE + j];
                const float s2 = SIMg[(i0 + 2) * SIM_STRIDE + j];
                #pragma unroll
                for (int cc = 0; cc < 4; ++cc) {
                    const float vv = V[(c0 + cc) * QKV_STRIDE + j];
                    acc[cc][0] += s0 * (vv + w[cc][11 - jj]);
                    acc[cc][1] += s1 * (vv + w[cc][12 - jj]);
                    acc[cc][2] += s2 * (vv + w[cc][13 - jj]);
                }
            }
            #pragma unroll
            for (int cc = 0; cc < 4; ++cc)
                #pragma unroll
                for (int ii = 0; ii < 3; ++ii) {
                    acc[cc][ii] += __shfl_xor_sync(0xffffffffu, acc[cc][ii], 1);
                    acc[cc][ii] += __shfl_xor_sync(0xffffffffu, acc[cc][ii], 2);
                }
            const int c = c0 + jq;
            #pragma unroll
            for (int ii = 0; ii < 3; ++ii) {
                const float av = (jq == 0) ? acc[0][ii] :
                                 (jq == 1) ? acc[1][ii] :
                                 (jq == 2) ? acc[2][ii] : acc[3][ii];
                const int i = i0 + ii;
                sOut[i * OUT_STRIDE + 8 * (gp + grp) + c] = av * sGO[i] + sBO[i];
            }
        }
        __syncthreads();
    }

    // ---- write out: out[0, i, wi, li, p] ----
    for (int idx = tid; idx < KS * 64; idx += NT) {
        const int i = idx >> 6, p = idx & 63;
        out[((i * KS + wi) * KS + li) * 64 + p] = sOut[i * OUT_STRIDE + p];
    }
}

extern "C" void kernel_launch(void* const* d_in, const int* in_sizes, int n_in,
                              void* d_out, int out_size) {
    (void)in_sizes; (void)n_in; (void)out_size;
    cudaFuncSetAttribute(axial_kernel, cudaFuncAttributeMaxDynamicSharedMemorySize, SMEM_BYTES);
    axial_kernel<<<KS * KS, NT, SMEM_BYTES>>>(
        (const float*)d_in[0], (const float*)d_in[1], (const float*)d_in[2],
        (const float*)d_in[3], (const float*)d_in[4], (const float*)d_in[5],
        (const float*)d_in[6], (const float*)d_in[7], (const float*)d_in[8],
        (float*)d_out);
}

// round 9
// speedup vs baseline: 1.3573x; 1.0104x over previous
#include <cuda_runtime.h>

#define KS 48
#define NT 256

typedef unsigned long long ull;

// strides (floats)
constexpr int SX_STRIDE  = 50;   // X[c][h]
constexpr int W_STRIDE   = 65;   // W[o][c]
constexpr int QKV_STRIDE = 49;   // QKV[o][h]
constexpr int REL_STRIDE = 97;   // rel[c][d]
constexpr int QK_STRIDE  = 50;   // QR/KR [48][50]  (even: ull loads)
constexpr int SIM_STRIDE = 51;   // SIM   [48][51]
constexpr int OUT_STRIDE = 65;   // out[i][p]

constexpr int QK_G  = 48 * QK_STRIDE + 16;  // 2416: ≡16 mod 32
constexpr int SIM_G = 48 * SIM_STRIDE;      // 2448

constexpr int OFF_QKV = 0;                              // 6272
constexpr int OFF_REL = OFF_QKV + 128 * QKV_STRIDE;     // +1552
constexpr int OFF_OUT = OFF_REL + 16 * REL_STRIDE;      // +3120
constexpr int OFF_PAR = OFF_OUT + 48 * OUT_STRIDE;      // +288
constexpr int OFF_SCR = OFF_PAR + 6 * 48;               // 11232
constexpr int OFF_X   = OFF_SCR;
constexpr int OFF_W   = OFF_X + 64 * SX_STRIDE;
constexpr int OFF_QR  = OFF_SCR;
constexpr int OFF_KR  = OFF_QR + 2 * QK_G;
constexpr int OFF_SIM = OFF_KR + 2 * QK_G;
constexpr int SCR_FLOATS  = 4 * QK_G + 2 * SIM_G;        // 14560 > 11520
constexpr int SMEM_FLOATS = OFF_SCR + SCR_FLOATS;        // 25792
constexpr int SMEM_BYTES  = SMEM_FLOATS * 4;             // 103168 B -> 2 CTAs/SM

__device__ __forceinline__ ull dupf(float v) {
    ull r; unsigned u = __float_as_uint(v);
    asm("mov.b64 %0, {%1, %1};" : "=l"(r) : "r"(u));
    return r;
}
__device__ __forceinline__ void ffma2(ull& d, ull a, ull b) {
    asm("fma.rn.f32x2 %0, %1, %2, %0;" : "+l"(d) : "l"(a), "l"(b));
}
__device__ __forceinline__ float f2lo(ull v) { return __uint_as_float((unsigned)(v & 0xffffffffull)); }
__device__ __forceinline__ float f2hi(ull v) { return __uint_as_float((unsigned)(v >> 32)); }

__global__ void __launch_bounds__(NT, 2) axial_kernel(
    const float* __restrict__ x,      const float* __restrict__ w_qkv,
    const float* __restrict__ relv,
    const float* __restrict__ g_qkv,  const float* __restrict__ b_qkv,
    const float* __restrict__ g_sim,  const float* __restrict__ b_sim,
    const float* __restrict__ g_out,  const float* __restrict__ b_out,
    float* __restrict__ out)
{
    extern __shared__ float sm[];
    float* sX   = sm + OFF_X;
    float* sW   = sm + OFF_W;
    float* sQKV = sm + OFF_QKV;
    float* sRel = sm + OFF_REL;
    float* sOut = sm + OFF_OUT;
    float* sGQ  = sm + OFF_PAR;
    float* sBQ  = sGQ + 48; float* sGS = sBQ + 48; float* sBS = sGS + 48;
    float* sGO  = sBS + 48; float* sBO = sGO + 48;

    const int tid = threadIdx.x;
    const int blk = blockIdx.x;
    const int wi = blk / KS, li = blk % KS;

    // ---- load X (as [c][h]), W, relative, BN params ----
    for (int idx = tid; idx < KS * 64; idx += NT) {
        const int h = idx >> 6, c = idx & 63;
        sX[c * SX_STRIDE + h] = x[((h * KS + wi) * KS + li) * 64 + c];
    }
    for (int idx = tid; idx < 128 * 64; idx += NT)
        sW[(idx >> 6) * W_STRIDE + (idx & 63)] = w_qkv[idx];
    for (int idx = tid; idx < 16 * 95; idx += NT)
        sRel[(idx / 95) * REL_STRIDE + (idx % 95)] = relv[idx];
    if (tid < KS) {
        const float inv = rsqrtf(1.001f);
        sGQ[tid] = g_qkv[tid] * inv; sBQ[tid] = b_qkv[tid];
        sGS[tid] = g_sim[tid] * inv; sBS[tid] = 3.0f * b_sim[tid];
        sGO[tid] = g_out[tid] * inv; sBO[tid] = 2.0f * b_out[tid];
    }
    __syncthreads();

    // ---- QKV = BN(W @ X): 128x48, 4o x 6h tiles (256 tiles) ----
    {
        const int o0 = (tid >> 3) * 4;
        const int h0 = (tid & 7) * 6;
        ull a[4][3];
        #pragma unroll
        for (int q = 0; q < 4; ++q)
            #pragma unroll
            for (int p = 0; p < 3; ++p) a[q][p] = 0ull;
        const float* xrow = sX + h0;
        #pragma unroll 4
        for (int c = 0; c < 64; ++c) {
            const ull* xp = reinterpret_cast<const ull*>(xrow + c * SX_STRIDE);
            const ull x01 = xp[0], x23 = xp[1], x45 = xp[2];
            #pragma unroll
            for (int q = 0; q < 4; ++q) {
                const ull wd = dupf(sW[(o0 + q) * W_STRIDE + c]);
                ffma2(a[q][0], wd, x01);
                ffma2(a[q][1], wd, x23);
                ffma2(a[q][2], wd, x45);
            }
        }
        float gg[6], bb[6];
        #pragma unroll
        for (int p = 0; p < 6; ++p) { gg[p] = sGQ[h0 + p]; bb[p] = sBQ[h0 + p]; }
        #pragma unroll
        for (int q = 0; q < 4; ++q) {
            float* dst = sQKV + (o0 + q) * QKV_STRIDE + h0;
            #pragma unroll
            for (int p = 0; p < 3; ++p) {
                dst[2 * p]     = f2lo(a[q][p]) * gg[2 * p]     + bb[2 * p];
                dst[2 * p + 1] = f2hi(a[q][p]) * gg[2 * p + 1] + bb[2 * p + 1];
            }
        }
    }
    __syncthreads();

    // ---- 4 passes, 2 groups each ----
    for (int gp = 0; gp < 8; gp += 2) {

        // == qr/kr: 2304 quad-tasks, scattered-i (conflict-free rel windows) ==
        for (int q = tid; q < 2304; q += NT) {
            if (q < 1152) {
                const int grp = q / 576; const int r = q - grp * 576;
                const int m = r / 12, il = r % 12;
                const float* Q = sQKV + (16 * (gp + grp)) * QKV_STRIDE;
                float* QRg = sm + OFF_QR + grp * QK_G;
                float a0 = 0.f, a1 = 0.f, a2 = 0.f, a3 = 0.f;
                #pragma unroll
                for (int c = 0; c < 4; ++c) {
                    const float qc = Q[c * QKV_STRIDE + m];
                    const float* rl = sRel + c * REL_STRIDE + (m - il + 47);
                    a0 += qc * rl[0];   a1 += qc * rl[-12];
                    a2 += qc * rl[-24]; a3 += qc * rl[-36];
                }
                float* d = QRg + m * QK_STRIDE + il;
                d[0] = a0; d[12] = a1; d[24] = a2; d[36] = a3;
            } else {
                int r = q - 1152; const int grp = r / 576; r -= grp * 576;
                const int j = r / 12, ml = r % 12;
                const float* Kp = sQKV + (16 * (gp + grp) + 4) * QKV_STRIDE;
                float* KRg = sm + OFF_KR + grp * QK_G;
                float a0 = 0.f, a1 = 0.f, a2 = 0.f, a3 = 0.f;
                #pragma unroll
                for (int c = 0; c < 4; ++c) {
                    const float kc = Kp[c * QKV_STRIDE + j];
                    const float* rl = sRel + (4 + c) * REL_STRIDE + (j - ml + 47);
                    a0 += kc * rl[0];   a1 += kc * rl[-12];
                    a2 += kc * rl[-24]; a3 += kc * rl[-36];
                }
                KRg[ml * QK_STRIDE + j]        = a0;
                KRg[(ml + 12) * QK_STRIDE + j] = a1;
                KRg[(ml + 24) * QK_STRIDE + j] = a2;
                KRg[(ml + 36) * QK_STRIDE + j] = a3;
            }
        }
        __syncthreads();

        // == qk: 6x6 tiles; balanced warp map (4 i0 x 4 j0 per warp) so both
        //    q and k loads dedup; k loaded as ull pairs; m-split lane pairs ==
        {
            const int mhalf = tid & 1;
            const int tile  = tid >> 1;          // 0..127
            const int grp   = tile >> 6;
            const int tt    = tile & 63;
            // i0 from bits {0,1,4}; j0 from bits {2,3,5} (bijective over 64)
            const int i0    = ((tt & 3)        + ((tt >> 4) & 1) * 4) * 6;
            const int j0    = (((tt >> 2) & 3) + ((tt >> 5) & 1) * 4) * 6;
            const float* QRg = sm + OFF_QR + grp * QK_G;
            const float* KRg = sm + OFF_KR + grp * QK_G;
            float* SIMg = sm + OFF_SIM + grp * SIM_G;

            ull acc[3][6];
            #pragma unroll
            for (int p = 0; p < 3; ++p)
                #pragma unroll
                for (int jj = 0; jj < 6; ++jj) acc[p][jj] = 0ull;

            const int mbase = mhalf * 24;
            #pragma unroll 4
            for (int mm = 0; mm < 24; ++mm) {
                const float* qp = QRg + (mbase + mm) * QK_STRIDE + i0;
                const ull q01 = reinterpret_cast<const ull*>(qp)[0];
                const ull q23 = reinterpret_cast<const ull*>(qp)[1];
                const ull q45 = reinterpret_cast<const ull*>(qp)[2];
                const float* kp = KRg + (mbase + mm) * QK_STRIDE + j0;
                const ull k01 = reinterpret_cast<const ull*>(kp)[0];
                const ull k23 = reinterpret_cast<const ull*>(kp)[1];
                const ull k45 = reinterpret_cast<const ull*>(kp)[2];
                const ull kd[6] = {dupf(f2lo(k01)), dupf(f2hi(k01)),
                                   dupf(f2lo(k23)), dupf(f2hi(k23)),
                                   dupf(f2lo(k45)), dupf(f2hi(k45))};
                #pragma unroll
                for (int jj = 0; jj < 6; ++jj) {
                    ffma2(acc[0][jj], q01, kd[jj]);
                    ffma2(acc[1][jj], q23, kd[jj]);
                    ffma2(acc[2][jj], q45, kd[jj]);
                }
            }
            // combine m-halves across the lane pair
            float full[6][6];
            #pragma unroll
            for (int p = 0; p < 3; ++p)
                #pragma unroll
                for (int jj = 0; jj < 6; ++jj) {
                    const ull other = __shfl_xor_sync(0xffffffffu, acc[p][jj], 1);
                    full[2 * p][jj]     = f2lo(acc[p][jj]) + f2lo(other);
                    full[2 * p + 1][jj] = f2hi(acc[p][jj]) + f2hi(other);
                }
            // each lane writes 3 rows; vectorized qrow/krow reads
            const int rbase = mhalf * 3;
            #pragma unroll
            for (int rr = 0; rr < 3; ++rr) {
                const int i = i0 + rbase + rr;
                const ull* qrp = reinterpret_cast<const ull*>(QRg + i * QK_STRIDE + j0);
                const ull* krp = reinterpret_cast<const ull*>(KRg + i * QK_STRIDE + j0);
                const ull qr01 = qrp[0], qr23 = qrp[1], qr45 = qrp[2];
                const ull kr01 = krp[0], kr23 = krp[1], kr45 = krp[2];
                const float qv[6] = {f2lo(qr01), f2hi(qr01), f2lo(qr23),
                                     f2hi(qr23), f2lo(qr45), f2hi(qr45)};
                const float kv[6] = {f2lo(kr01), f2hi(kr01), f2lo(kr23),
                                     f2hi(kr23), f2lo(kr45), f2hi(kr45)};
                float* srow = SIMg + i * SIM_STRIDE + j0;
                #pragma unroll
                for (int jj = 0; jj < 6; ++jj) {
                    const int j = j0 + jj;
                    const float v = full[rbase + rr][jj] + qv[jj] + kv[jj];
                    srow[jj] = v * sGS[j] + sBS[j];
                }
            }
        }
        __syncthreads();

        // == softmax: 96 rows as 48 pairs; 16 lanes/row, 3 j per lane ==
        {
            const int lane = tid & 31, wp = tid >> 5;
            const int half16 = lane >> 4;
            const int jb = (lane & 15) * 3;
            for (int rp = wp; rp < 48; rp += 8) {
                float* row = sm + OFF_SIM + (2 * rp + half16) * SIM_STRIDE;
                const float v0 = row[jb], v1 = row[jb + 1], v2 = row[jb + 2];
                float mx = fmaxf(v0, fmaxf(v1, v2));
                #pragma unroll
                for (int off = 1; off < 16; off <<= 1)
                    mx = fmaxf(mx, __shfl_xor_sync(0xffffffffu, mx, off));
                const float e0 = __expf(v0 - mx);
                const float e1 = __expf(v1 - mx);
                const float e2 = __expf(v2 - mx);
                float s = e0 + e1 + e2;
                #pragma unroll
                for (int off = 1; off < 16; off <<= 1)
                    s += __shfl_xor_sync(0xffffffffu, s, off);
                const float rinv = __fdividef(1.0f, s);
                row[jb] = e0 * rinv; row[jb + 1] = e1 * rinv; row[jb + 2] = e2 * rinv;
            }
        }
        __syncthreads();

        // == sv: 4c x 3i tiles x 4 j-splits; rel windows preloaded, shfl reduce ==
        {
            const int jq   = tid & 3;
            const int tile = tid >> 2;           // 0..63
            const int grp  = tile >> 5;
            const int tt   = tile & 31;
            const int c0   = (tt >> 4) * 4;
            const int i0   = (tt & 15) * 3;
            const float* SIMg = sm + OFF_SIM + grp * SIM_G;
            const float* V = sQKV + (16 * (gp + grp) + 8) * QKV_STRIDE;
            const int jb = jq * 12;

            float w[4][14];
            #pragma unroll
            for (int cc = 0; cc < 4; ++cc) {
                const float* base = sRel + (8 + c0 + cc) * REL_STRIDE + (i0 - jb + 36);
                #pragma unroll
                for (int t = 0; t < 14; ++t) w[cc][t] = base[t];
            }

            float acc[4][3];
            #pragma unroll
            for (int cc = 0; cc < 4; ++cc)
                #pragma unroll
                for (int ii = 0; ii < 3; ++ii) acc[cc][ii] = 0.f;

            #pragma unroll
            for (int jj = 0; jj < 12; ++jj) {
                const int j = jb + jj;
                const float s0 = SIMg[i0 * SIM_STRIDE + j];
                const float s1 = SIMg[(i0 + 1) * SIM_STRIDE + j];
                const float s2 = SIMg[(i0 + 2) * SIM_STRIDE + j];
                #pragma unroll
                for (int cc = 0; cc < 4; ++cc) {
                    const float vv = V[(c0 + cc) * QKV_STRIDE + j];
                    acc[cc][0] += s0 * (vv + w[cc][11 - jj]);
                    acc[cc][1] += s1 * (vv + w[cc][12 - jj]);
                    acc[cc][2] += s2 * (vv + w[cc][13 - jj]);
                }
            }
            #pragma unroll
            for (int cc = 0; cc < 4; ++cc)
                #pragma unroll
                for (int ii = 0; ii < 3; ++ii) {
                    acc[cc][ii] += __shfl_xor_sync(0xffffffffu, acc[cc][ii], 1);
                    acc[cc][ii] += __shfl_xor_sync(0xffffffffu, acc[cc][ii], 2);
                }
            const int c = c0 + jq;
            #pragma unroll
            for (int ii = 0; ii < 3; ++ii) {
                const float av = (jq == 0) ? acc[0][ii] :
                                 (jq == 1) ? acc[1][ii] :
                                 (jq == 2) ? acc[2][ii] : acc[3][ii];
                const int i = i0 + ii;
                sOut[i * OUT_STRIDE + 8 * (gp + grp) + c] = av * sGO[i] + sBO[i];
            }
        }
        __syncthreads();
    }

    // ---- write out ----
    for (int idx = tid; idx < KS * 64; idx += NT) {
        const int i = idx >> 6, p = idx & 63;
        out[((i * KS + wi) * KS + li) * 64 + p] = sOut[i * OUT_STRIDE + p];
    }
}

extern "C" void kernel_launch(void* const* d_in, const int* in_sizes, int n_in,
                              void* d_out, int out_size) {
    (void)in_sizes; (void)n_in; (void)out_size;
    cudaFuncSetAttribute(axial_kernel, cudaFuncAttributeMaxDynamicSharedMemorySize, SMEM_BYTES);
    axial_kernel<<<KS * KS, NT, SMEM_BYTES>>>(
        (const float*)d_in[0], (const float*)d_in[1], (const float*)d_in[2],
        (const float*)d_in[3], (const float*)d_in[4], (const float*)d_in[5],
        (const float*)d_in[6], (const float*)d_in[7], (const float*)d_in[8],
        (float*)d_out);
}

// round 10
// speedup vs baseline: 1.3823x; 1.0184x over previous
#include <cuda_runtime.h>

#define KS 48
#define NT 256

typedef unsigned long long ull;

// strides (floats)
constexpr int SX_STRIDE  = 50;   // X[c][h]
constexpr int W_STRIDE   = 65;   // W[o][c]
constexpr int QKV_STRIDE = 49;   // QKV[o][h]
constexpr int REL_STRIDE = 97;   // rel[c][d]
constexpr int QK_STRIDE  = 50;   // QR/KR [48][50]  (even: ull loads)
constexpr int SIM_STRIDE = 51;   // SIM   [48][51]

constexpr int QK_G  = 48 * QK_STRIDE + 16;  // 2416: ≡16 mod 32
constexpr int SIM_G = 48 * SIM_STRIDE;      // 2448

constexpr int OFF_QKV = 0;                              // 6272
constexpr int OFF_REL = OFF_QKV + 128 * QKV_STRIDE;     // +1552
constexpr int OFF_PAR = OFF_REL + 16 * REL_STRIDE;      // +288
constexpr int OFF_SCR = OFF_PAR + 6 * 48;               // 8112
constexpr int OFF_X   = OFF_SCR;
constexpr int OFF_W   = OFF_X + 64 * SX_STRIDE;
constexpr int OFF_QR  = OFF_SCR;
constexpr int OFF_KR  = OFF_QR + 2 * QK_G;
constexpr int OFF_SIM = OFF_KR + 2 * QK_G;
constexpr int SCR_FLOATS  = 4 * QK_G + 2 * SIM_G;        // 14560 > 11520 (X+W)
constexpr int SMEM_FLOATS = OFF_SCR + SCR_FLOATS;        // 22672
constexpr int SMEM_BYTES  = SMEM_FLOATS * 4;             // 90688 B -> 2 CTAs/SM

constexpr int OUT_PLANE_STRIDE = KS * KS * 64;           // i-stride in out

__device__ __forceinline__ ull dupf(float v) {
    ull r; unsigned u = __float_as_uint(v);
    asm("mov.b64 %0, {%1, %1};" : "=l"(r) : "r"(u));
    return r;
}
__device__ __forceinline__ void ffma2(ull& d, ull a, ull b) {
    asm("fma.rn.f32x2 %0, %1, %2, %0;" : "+l"(d) : "l"(a), "l"(b));
}
__device__ __forceinline__ float f2lo(ull v) { return __uint_as_float((unsigned)(v & 0xffffffffull)); }
__device__ __forceinline__ float f2hi(ull v) { return __uint_as_float((unsigned)(v >> 32)); }

__global__ void __launch_bounds__(NT, 2) axial_kernel(
    const float* __restrict__ x,      const float* __restrict__ w_qkv,
    const float* __restrict__ relv,
    const float* __restrict__ g_qkv,  const float* __restrict__ b_qkv,
    const float* __restrict__ g_sim,  const float* __restrict__ b_sim,
    const float* __restrict__ g_out,  const float* __restrict__ b_out,
    float* __restrict__ out)
{
    extern __shared__ float sm[];
    float* sX   = sm + OFF_X;
    float* sW   = sm + OFF_W;
    float* sQKV = sm + OFF_QKV;
    float* sRel = sm + OFF_REL;
    float* sGQ  = sm + OFF_PAR;
    float* sBQ  = sGQ + 48; float* sGS = sBQ + 48; float* sBS = sGS + 48;
    float* sGO  = sBS + 48; float* sBO = sGO + 48;

    const int tid = threadIdx.x;
    const int blk = blockIdx.x;
    const int wi = blk / KS, li = blk % KS;

    // ---- load X (as [c][h]), W, relative, BN params ----
    for (int idx = tid; idx < KS * 64; idx += NT) {
        const int h = idx >> 6, c = idx & 63;
        sX[c * SX_STRIDE + h] = x[((h * KS + wi) * KS + li) * 64 + c];
    }
    for (int idx = tid; idx < 128 * 64; idx += NT)
        sW[(idx >> 6) * W_STRIDE + (idx & 63)] = w_qkv[idx];
    for (int idx = tid; idx < 16 * 95; idx += NT)
        sRel[(idx / 95) * REL_STRIDE + (idx % 95)] = relv[idx];
    if (tid < KS) {
        const float inv = rsqrtf(1.001f);
        sGQ[tid] = g_qkv[tid] * inv; sBQ[tid] = b_qkv[tid];
        sGS[tid] = g_sim[tid] * inv; sBS[tid] = 3.0f * b_sim[tid];
        sGO[tid] = g_out[tid] * inv; sBO[tid] = 2.0f * b_out[tid];
    }
    __syncthreads();

    // ---- QKV = BN(W @ X): 128x48, 4o x 6h tiles (256 tiles) ----
    {
        const int o0 = (tid >> 3) * 4;
        const int h0 = (tid & 7) * 6;
        ull a[4][3];
        #pragma unroll
        for (int q = 0; q < 4; ++q)
            #pragma unroll
            for (int p = 0; p < 3; ++p) a[q][p] = 0ull;
        const float* xrow = sX + h0;
        #pragma unroll 4
        for (int c = 0; c < 64; ++c) {
            const ull* xp = reinterpret_cast<const ull*>(xrow + c * SX_STRIDE);
            const ull x01 = xp[0], x23 = xp[1], x45 = xp[2];
            #pragma unroll
            for (int q = 0; q < 4; ++q) {
                const ull wd = dupf(sW[(o0 + q) * W_STRIDE + c]);
                ffma2(a[q][0], wd, x01);
                ffma2(a[q][1], wd, x23);
                ffma2(a[q][2], wd, x45);
            }
        }
        float gg[6], bb[6];
        #pragma unroll
        for (int p = 0; p < 6; ++p) { gg[p] = sGQ[h0 + p]; bb[p] = sBQ[h0 + p]; }
        #pragma unroll
        for (int q = 0; q < 4; ++q) {
            float* dst = sQKV + (o0 + q) * QKV_STRIDE + h0;
            #pragma unroll
            for (int p = 0; p < 3; ++p) {
                dst[2 * p]     = f2lo(a[q][p]) * gg[2 * p]     + bb[2 * p];
                dst[2 * p + 1] = f2hi(a[q][p]) * gg[2 * p + 1] + bb[2 * p + 1];
            }
        }
    }
    __syncthreads();

    // ---- 4 passes, 2 groups each (3 barriers per pass) ----
    for (int gp = 0; gp < 8; gp += 2) {

        // == qr/kr: 2304 quad-tasks, scattered-i (conflict-free rel windows) ==
        // Safe without a barrier after sv: QR/KR are not touched by sv, and the
        // qk->softmax barrier of the previous pass ordered all qk reads of QR/KR
        // before any warp could reach this point.
        for (int q = tid; q < 2304; q += NT) {
            if (q < 1152) {
                const int grp = q / 576; const int r = q - grp * 576;
                const int m = r / 12, il = r % 12;
                const float* Q = sQKV + (16 * (gp + grp)) * QKV_STRIDE;
                float* QRg = sm + OFF_QR + grp * QK_G;
                float a0 = 0.f, a1 = 0.f, a2 = 0.f, a3 = 0.f;
                #pragma unroll
                for (int c = 0; c < 4; ++c) {
                    const float qc = Q[c * QKV_STRIDE + m];
                    const float* rl = sRel + c * REL_STRIDE + (m - il + 47);
                    a0 += qc * rl[0];   a1 += qc * rl[-12];
                    a2 += qc * rl[-24]; a3 += qc * rl[-36];
                }
                float* d = QRg + m * QK_STRIDE + il;
                d[0] = a0; d[12] = a1; d[24] = a2; d[36] = a3;
            } else {
                int r = q - 1152; const int grp = r / 576; r -= grp * 576;
                const int j = r / 12, ml = r % 12;
                const float* Kp = sQKV + (16 * (gp + grp) + 4) * QKV_STRIDE;
                float* KRg = sm + OFF_KR + grp * QK_G;
                float a0 = 0.f, a1 = 0.f, a2 = 0.f, a3 = 0.f;
                #pragma unroll
                for (int c = 0; c < 4; ++c) {
                    const float kc = Kp[c * QKV_STRIDE + j];
                    const float* rl = sRel + (4 + c) * REL_STRIDE + (j - ml + 47);
                    a0 += kc * rl[0];   a1 += kc * rl[-12];
                    a2 += kc * rl[-24]; a3 += kc * rl[-36];
                }
                KRg[ml * QK_STRIDE + j]        = a0;
                KRg[(ml + 12) * QK_STRIDE + j] = a1;
                KRg[(ml + 24) * QK_STRIDE + j] = a2;
                KRg[(ml + 36) * QK_STRIDE + j] = a3;
            }
        }
        __syncthreads();

        // == qk: 6x6 tiles; balanced warp map; m-split lane pairs, shfl reduce ==
        {
            const int mhalf = tid & 1;
            const int tile  = tid >> 1;          // 0..127
            const int grp   = tile >> 6;
            const int tt    = tile & 63;
            const int i0    = ((tt & 3)        + ((tt >> 4) & 1) * 4) * 6;
            const int j0    = (((tt >> 2) & 3) + ((tt >> 5) & 1) * 4) * 6;
            const float* QRg = sm + OFF_QR + grp * QK_G;
            const float* KRg = sm + OFF_KR + grp * QK_G;
            float* SIMg = sm + OFF_SIM + grp * SIM_G;

            ull acc[3][6];
            #pragma unroll
            for (int p = 0; p < 3; ++p)
                #pragma unroll
                for (int jj = 0; jj < 6; ++jj) acc[p][jj] = 0ull;

            const int mbase = mhalf * 24;
            #pragma unroll 4
            for (int mm = 0; mm < 24; ++mm) {
                const float* qp = QRg + (mbase + mm) * QK_STRIDE + i0;
                const ull q01 = reinterpret_cast<const ull*>(qp)[0];
                const ull q23 = reinterpret_cast<const ull*>(qp)[1];
                const ull q45 = reinterpret_cast<const ull*>(qp)[2];
                const float* kp = KRg + (mbase + mm) * QK_STRIDE + j0;
                const ull k01 = reinterpret_cast<const ull*>(kp)[0];
                const ull k23 = reinterpret_cast<const ull*>(kp)[1];
                const ull k45 = reinterpret_cast<const ull*>(kp)[2];
                const ull kd[6] = {dupf(f2lo(k01)), dupf(f2hi(k01)),
                                   dupf(f2lo(k23)), dupf(f2hi(k23)),
                                   dupf(f2lo(k45)), dupf(f2hi(k45))};
                #pragma unroll
                for (int jj = 0; jj < 6; ++jj) {
                    ffma2(acc[0][jj], q01, kd[jj]);
                    ffma2(acc[1][jj], q23, kd[jj]);
                    ffma2(acc[2][jj], q45, kd[jj]);
                }
            }
            float full[6][6];
            #pragma unroll
            for (int p = 0; p < 3; ++p)
                #pragma unroll
                for (int jj = 0; jj < 6; ++jj) {
                    const ull other = __shfl_xor_sync(0xffffffffu, acc[p][jj], 1);
                    full[2 * p][jj]     = f2lo(acc[p][jj]) + f2lo(other);
                    full[2 * p + 1][jj] = f2hi(acc[p][jj]) + f2hi(other);
                }
            const int rbase = mhalf * 3;
            #pragma unroll
            for (int rr = 0; rr < 3; ++rr) {
                const int i = i0 + rbase + rr;
                const ull* qrp = reinterpret_cast<const ull*>(QRg + i * QK_STRIDE + j0);
                const ull* krp = reinterpret_cast<const ull*>(KRg + i * QK_STRIDE + j0);
                const ull qr01 = qrp[0], qr23 = qrp[1], qr45 = qrp[2];
                const ull kr01 = krp[0], kr23 = krp[1], kr45 = krp[2];
                const float qv[6] = {f2lo(qr01), f2hi(qr01), f2lo(qr23),
                                     f2hi(qr23), f2lo(qr45), f2hi(qr45)};
                const float kv[6] = {f2lo(kr01), f2hi(kr01), f2lo(kr23),
                                     f2hi(kr23), f2lo(kr45), f2hi(kr45)};
                float* srow = SIMg + i * SIM_STRIDE + j0;
                #pragma unroll
                for (int jj = 0; jj < 6; ++jj) {
                    const int j = j0 + jj;
                    const float v = full[rbase + rr][jj] + qv[jj] + kv[jj];
                    srow[jj] = v * sGS[j] + sBS[j];
                }
            }
        }
        __syncthreads();

        // == softmax: 96 rows as 48 pairs; 16 lanes/row, 3 j per lane ==
        {
            const int lane = tid & 31, wp = tid >> 5;
            const int half16 = lane >> 4;
            const int jb = (lane & 15) * 3;
            for (int rp = wp; rp < 48; rp += 8) {
                float* row = sm + OFF_SIM + (2 * rp + half16) * SIM_STRIDE;
                const float v0 = row[jb], v1 = row[jb + 1], v2 = row[jb + 2];
                float mx = fmaxf(v0, fmaxf(v1, v2));
                #pragma unroll
                for (int off = 1; off < 16; off <<= 1)
                    mx = fmaxf(mx, __shfl_xor_sync(0xffffffffu, mx, off));
                const float e0 = __expf(v0 - mx);
                const float e1 = __expf(v1 - mx);
                const float e2 = __expf(v2 - mx);
                float s = e0 + e1 + e2;
                #pragma unroll
                for (int off = 1; off < 16; off <<= 1)
                    s += __shfl_xor_sync(0xffffffffu, s, off);
                const float rinv = __fdividef(1.0f, s);
                row[jb] = e0 * rinv; row[jb + 1] = e1 * rinv; row[jb + 2] = e2 * rinv;
            }
        }
        __syncthreads();

        // == sv: 4c x 3i tiles x 4 j-splits; rel windows preloaded, shfl reduce;
        //    final BN'd values STG'd straight to gmem (no smem staging) ==
        {
            const int jq   = tid & 3;
            const int tile = tid >> 2;           // 0..63
            const int grp  = tile >> 5;
            const int tt   = tile & 31;
            const int c0   = (tt >> 4) * 4;
            const int i0   = (tt & 15) * 3;
            const float* SIMg = sm + OFF_SIM + grp * SIM_G;
            const float* V = sQKV + (16 * (gp + grp) + 8) * QKV_STRIDE;
            const int jb = jq * 12;

            float w[4][14];
            #pragma unroll
            for (int cc = 0; cc < 4; ++cc) {
                const float* base = sRel + (8 + c0 + cc) * REL_STRIDE + (i0 - jb + 36);
                #pragma unroll
                for (int t = 0; t < 14; ++t) w[cc][t] = base[t];
            }

            float acc[4][3];
            #pragma unroll
            for (int cc = 0; cc < 4; ++cc)
                #pragma unroll
                for (int ii = 0; ii < 3; ++ii) acc[cc][ii] = 0.f;

            #pragma unroll
            for (int jj = 0; jj < 12; ++jj) {
                const int j = jb + jj;
                const float s0 = SIMg[i0 * SIM_STRIDE + j];
                const float s1 = SIMg[(i0 + 1) * SIM_STRIDE + j];
                const float s2 = SIMg[(i0 + 2) * SIM_STRIDE + j];
                #pragma unroll
                for (int cc = 0; cc < 4; ++cc) {
                    const float vv = V[(c0 + cc) * QKV_STRIDE + j];
                    acc[cc][0] += s0 * (vv + w[cc][11 - jj]);
                    acc[cc][1] += s1 * (vv + w[cc][12 - jj]);
                    acc[cc][2] += s2 * (vv + w[cc][13 - jj]);
                }
            }
            #pragma unroll
            for (int cc = 0; cc < 4; ++cc)
                #pragma unroll
                for (int ii = 0; ii < 3; ++ii) {
                    acc[cc][ii] += __shfl_xor_sync(0xffffffffu, acc[cc][ii], 1);
                    acc[cc][ii] += __shfl_xor_sync(0xffffffffu, acc[cc][ii], 2);
                }
            const int c = c0 + jq;
            float* op = out + ((i0 * KS + wi) * KS + li) * 64 + 8 * (gp + grp) + c;
            #pragma unroll
            for (int ii = 0; ii < 3; ++ii) {
                const float av = (jq == 0) ? acc[0][ii] :
                                 (jq == 1) ? acc[1][ii] :
                                 (jq == 2) ? acc[2][ii] : acc[3][ii];
                const int i = i0 + ii;
                op[ii * OUT_PLANE_STRIDE] = av * sGO[i] + sBO[i];
            }
        }
        // no barrier: next pass's qr/kr touches only QR/KR (disjoint from SIM),
        // and its qk-barrier orders SIM writes after all sv reads.
    }
}

extern "C" void kernel_launch(void* const* d_in, const int* in_sizes, int n_in,
                              void* d_out, int out_size) {
    (void)in_sizes; (void)n_in; (void)out_size;
    cudaFuncSetAttribute(axial_kernel, cudaFuncAttributeMaxDynamicSharedMemorySize, SMEM_BYTES);
    axial_kernel<<<KS * KS, NT, SMEM_BYTES>>>(
        (const float*)d_in[0], (const float*)d_in[1], (const float*)d_in[2],
        (const float*)d_in[3], (const float*)d_in[4], (const float*)d_in[5],
        (const float*)d_in[6], (const float*)d_in[7], (const float*)d_in[8],
        (float*)d_out);
}